// round 6
// baseline (speedup 1.0000x reference)
#include <cuda_runtime.h>
#include <cstdint>

#define D_IN 1024
#define HID  256
#define G4   1024
#define MID  512
#define SEQ  512
#define NB   4
#define NOUT 50
#define SED  64
#define NPOS 30
#define WLD  1090           // 2*(MID+1) + SED
#define ROWS 2048           // NB*SEQ
#define CPG  8              // CTAs per recurrence group (== cluster size, portable)
#define UPC  (HID / CPG)    // hidden units per CTA = 32
#define NGRP 8              // 2 dirs * 4 batch

// ------------------------- scratch (static device memory) -------------------
__device__ float g_G[2][ROWS][G4];      // gate input preactivations (+bias)
__device__ float g_bias[2][G4];
__device__ float g_hcat[ROWS][MID];     // [b*SEQ+t][dir*HID + j]
__device__ float g_head[ROWS][MID];
__device__ float g_tail[ROWS][MID];
__device__ float g_shead[ROWS][NOUT];   // [(b,m)][k]
__device__ float g_stail[ROWS][NOUT];   // [(b,n)][k]
__device__ float g_sztab[NOUT][NPOS];

// ------------------------- prep: bias, size table ---------------------------
__global__ void prep_kernel(const float* __restrict__ bih_f, const float* __restrict__ bhh_f,
                            const float* __restrict__ bih_b, const float* __restrict__ bhh_b,
                            const float* __restrict__ emb,   const float* __restrict__ W)
{
    int g = blockIdx.x * blockDim.x + threadIdx.x;
    if (g < G4)            g_bias[0][g]      = bih_f[g]      + bhh_f[g];
    else if (g < 2 * G4)   g_bias[1][g - G4] = bih_b[g - G4] + bhh_b[g - G4];
    if (g < NOUT * NPOS) {
        int k = g / NPOS, p = g % NPOS;
        float s = 0.f;
        #pragma unroll 8
        for (int h = 0; h < SED; h++)
            s += emb[p * SED + h] * W[k * WLD + 2 * (MID + 1) + h];
        g_sztab[k][p] = s;
    }
}

// ------------------------- tf32 GEMM: C = A @ B^T (+bias, opt leaky) --------
__device__ __forceinline__ float to_tf32(float x) {
    uint32_t u;
    asm("cvt.rna.tf32.f32 %0, %1;" : "=r"(u) : "f"(x));
    return __uint_as_float(u);
}

__global__ void __launch_bounds__(128) gemm_tf32(
    const float* __restrict__ A, int lda,
    const float* __restrict__ Bw, int ldb,
    const float* __restrict__ bias, int bstr,
    float* __restrict__ C, int ldc,
    int N, int K, int act)
{
    __shared__ float As[64][33];
    __shared__ float Bs[64][33];
    int tid  = threadIdx.x;
    int warp = tid >> 5, lane = tid & 31;
    int gq = lane >> 2, tg = lane & 3;
    int wm = (warp >> 1) * 32, wn = (warp & 1) * 32;
    int bm = blockIdx.y * 64, bn = blockIdx.x * 64;

    float acc[2][4][4];
    #pragma unroll
    for (int a = 0; a < 2; a++)
        #pragma unroll
        for (int b = 0; b < 4; b++)
            #pragma unroll
            for (int c = 0; c < 4; c++) acc[a][b][c] = 0.f;

    bool bvec = ((ldb & 3) == 0);

    for (int k0 = 0; k0 < K; k0 += 32) {
        #pragma unroll
        for (int i = 0; i < 4; i++) {
            int l4 = tid + i * 128;
            int r = l4 >> 3, c4 = (l4 & 7) << 2;
            const float4 v = *reinterpret_cast<const float4*>(A + (size_t)(bm + r) * lda + k0 + c4);
            As[r][c4 + 0] = to_tf32(v.x); As[r][c4 + 1] = to_tf32(v.y);
            As[r][c4 + 2] = to_tf32(v.z); As[r][c4 + 3] = to_tf32(v.w);
        }
        #pragma unroll
        for (int i = 0; i < 4; i++) {
            int l4 = tid + i * 128;
            int r = l4 >> 3, c4 = (l4 & 7) << 2;
            float4 v;
            if (bn + r < N) {
                if (bvec) {
                    v = *reinterpret_cast<const float4*>(Bw + (size_t)(bn + r) * ldb + k0 + c4);
                } else {
                    const float* p = Bw + (size_t)(bn + r) * ldb + k0 + c4;
                    v = make_float4(p[0], p[1], p[2], p[3]);
                }
            } else v = make_float4(0.f, 0.f, 0.f, 0.f);
            Bs[r][c4 + 0] = to_tf32(v.x); Bs[r][c4 + 1] = to_tf32(v.y);
            Bs[r][c4 + 2] = to_tf32(v.z); Bs[r][c4 + 3] = to_tf32(v.w);
        }
        __syncthreads();

        #pragma unroll
        for (int kk = 0; kk < 32; kk += 8) {
            uint32_t af[2][4], bf[4][2];
            #pragma unroll
            for (int mf = 0; mf < 2; mf++) {
                int r0 = wm + mf * 16 + gq;
                af[mf][0] = __float_as_uint(As[r0    ][kk + tg]);
                af[mf][1] = __float_as_uint(As[r0 + 8][kk + tg]);
                af[mf][2] = __float_as_uint(As[r0    ][kk + tg + 4]);
                af[mf][3] = __float_as_uint(As[r0 + 8][kk + tg + 4]);
            }
            #pragma unroll
            for (int nf = 0; nf < 4; nf++) {
                int n0 = wn + nf * 8 + gq;
                bf[nf][0] = __float_as_uint(Bs[n0][kk + tg]);
                bf[nf][1] = __float_as_uint(Bs[n0][kk + tg + 4]);
            }
            #pragma unroll
            for (int mf = 0; mf < 2; mf++)
                #pragma unroll
                for (int nf = 0; nf < 4; nf++)
                    asm volatile(
                        "mma.sync.aligned.m16n8k8.row.col.f32.tf32.tf32.f32 "
                        "{%0,%1,%2,%3}, {%4,%5,%6,%7}, {%8,%9}, {%0,%1,%2,%3};\n"
                        : "+f"(acc[mf][nf][0]), "+f"(acc[mf][nf][1]),
                          "+f"(acc[mf][nf][2]), "+f"(acc[mf][nf][3])
                        : "r"(af[mf][0]), "r"(af[mf][1]), "r"(af[mf][2]), "r"(af[mf][3]),
                          "r"(bf[nf][0]), "r"(bf[nf][1]));
        }
        __syncthreads();
    }

    #pragma unroll
    for (int mf = 0; mf < 2; mf++) {
        #pragma unroll
        for (int nf = 0; nf < 4; nf++) {
            int row = bm + wm + mf * 16 + gq;
            int col = bn + wn + nf * 8 + tg * 2;
            #pragma unroll
            for (int q = 0; q < 4; q++) {
                int r = row + (q >> 1) * 8;
                int c = col + (q & 1);
                if (c < N) {
                    float v = acc[mf][nf][q] + (bias ? bias[(size_t)c * bstr] : 0.f);
                    if (act) v = v > 0.f ? v : 0.01f * v;
                    C[(size_t)r * ldc + c] = v;
                }
            }
        }
    }
}

// ------------------------- LSTM recurrence (8-CTA cluster, flag sync) -------
// 8 groups (dir,batch), each = one 8-CTA cluster. CTA owns 32 hidden units.
// 512 threads = 16 warps; warp w = units {2w, 2w+1} (half-warp per unit).
// Sync protocol per step:
//   warp 0 acquire-polls local flags[8]; all warps rendezvous at __syncthreads.
//   After compute, producers push h (b64 pairs) to all peers' hs2[nxt];
//   __syncthreads; warp 0 lanes<8 release-store step+1 into peers' flags[cig].
//   The g_hcat global store is issued AFTER the release (off the chain).
__device__ __forceinline__ float sigm(float x) { return 1.f / (1.f + __expf(-x)); }
__device__ __forceinline__ float ftanh(float x) {
    float e = __expf(2.f * x);
    return 1.f - __fdividef(2.f, e + 1.f);
}

__device__ __forceinline__ void fma2(unsigned long long& acc,
                                     unsigned long long a, unsigned long long b) {
    asm("fma.rn.f32x2 %0, %1, %2, %0;" : "+l"(acc) : "l"(a), "l"(b));
}
__device__ __forceinline__ float pairsum(unsigned long long p) {
    uint32_t lo, hi;
    asm("mov.b64 {%0,%1}, %2;" : "=r"(lo), "=r"(hi) : "l"(p));
    return __uint_as_float(lo) + __uint_as_float(hi);
}

__global__ void __launch_bounds__(512, 1) __cluster_dims__(CPG, 1, 1)
lstm_kernel(const float* __restrict__ Whh_f, const float* __restrict__ Whh_b)
{
    __shared__ __align__(16) float    hs2[2][HID];
    __shared__ __align__(16) uint32_t flags[CPG];

    int grp = blockIdx.x / CPG;
    uint32_t cig;
    asm("mov.u32 %0, %%cluster_ctarank;" : "=r"(cig));
    int d = grp >> 2, b = grp & 3;
    int tid  = threadIdx.x;
    int w    = tid >> 5;            // warp 0..15
    int lane = tid & 31;
    int hl   = lane & 15;           // lane within unit
    int u    = 2 * w + (lane >> 4); // unit 0..31 within CTA
    int j    = (int)cig * UPC + u;  // global hidden unit
    const float* Whh = d ? Whh_b : Whh_f;
    const float* Gd  = &g_G[d][0][0];

    // weights: 4 gates x 4 k-chunks x (4 floats = 2 u64)
    ulonglong2 w2[4][4];
    #pragma unroll
    for (int gi = 0; gi < 4; gi++)
        #pragma unroll
        for (int c = 0; c < 4; c++)
            w2[gi][c] = *reinterpret_cast<const ulonglong2*>(
                &Whh[(size_t)(gi * HID + j) * HID + c * 64 + hl * 4]);

    if (tid < 2 * HID) ((float*)hs2)[tid] = 0.f;
    if (tid < CPG) flags[tid] = 0u;
    __syncthreads();
    asm volatile("barrier.cluster.arrive.aligned;" ::: "memory");
    asm volatile("barrier.cluster.wait.aligned;"  ::: "memory");

    uint32_t hs_u32  = (uint32_t)__cvta_generic_to_shared(&hs2[0][0]);
    uint32_t flg_u32 = (uint32_t)__cvta_generic_to_shared(&flags[0]);
    uint32_t my_flag_addr = flg_u32 + (uint32_t)(lane & 7) * 4u;

    // precompute remote addresses
    uint32_t ra[2][CPG];   // remote h slot (this warp's unit pair) per parity
    #pragma unroll
    for (int P = 0; P < 2; P++) {
        uint32_t laddr = hs_u32 + (uint32_t)(P * HID + (int)cig * UPC + 2 * w) * 4u;
        #pragma unroll
        for (int r = 0; r < CPG; r++)
            asm("mapa.shared::cluster.u32 %0, %1, %2;"
                : "=r"(ra[P][r]) : "r"(laddr), "r"(r));
    }
    uint32_t fa;           // remote flag slot (rank = lane), valid for lane<8
    {
        uint32_t laddr = flg_u32 + cig * 4u;
        asm("mapa.shared::cluster.u32 %0, %1, %2;"
            : "=r"(fa) : "r"(laddr), "r"(lane & 7));
    }

    float cst = 0.f;

    for (int st = 0; st < SEQ; st++) {
        int t = d ? (SEQ - 1 - st) : st;
        int cur = st & 1, nxt = cur ^ 1;

        // prefetch preactivations (independent of h) BEFORE the wait
        float gin[4];
        if (hl == 0) {
            size_t rbase = (size_t)(b * SEQ + t) * G4 + j;
            #pragma unroll
            for (int gi = 0; gi < 4; gi++) gin[gi] = __ldg(&Gd[rbase + gi * HID]);
        }

        // warp 0 polls; everyone else waits at the barrier (no spin storm)
        if (w == 0) {
            uint32_t tgt = (uint32_t)st;
            while (true) {
                uint32_t f = 0xffffffffu;
                if (lane < 8)
                    asm volatile("ld.acquire.cluster.shared::cta.u32 %0, [%1];"
                                 : "=r"(f) : "r"(my_flag_addr));
                if (__all_sync(0xffffffffu, f >= tgt)) break;
            }
        }
        __syncthreads();

        // matvec: 4 gate rows of unit u over this lane's 16 h values
        unsigned long long acc[4] = {0ull, 0ull, 0ull, 0ull};
        #pragma unroll
        for (int c = 0; c < 4; c++) {
            const ulonglong2 hv = *reinterpret_cast<const ulonglong2*>(
                &hs2[cur][c * 64 + hl * 4]);
            #pragma unroll
            for (int gi = 0; gi < 4; gi++) {
                fma2(acc[gi], w2[gi][c].x, hv.x);
                fma2(acc[gi], w2[gi][c].y, hv.y);
            }
        }
        float red[4];
        #pragma unroll
        for (int gi = 0; gi < 4; gi++) red[gi] = pairsum(acc[gi]);
        #pragma unroll
        for (int off = 8; off > 0; off >>= 1)
            #pragma unroll
            for (int gi = 0; gi < 4; gi++)
                red[gi] += __shfl_xor_sync(0xffffffffu, red[gi], off);

        float h = 0.f;
        if (hl == 0) {   // lanes 0 and 16: per-unit results
            float iv = sigm (red[0] + gin[0]);
            float fv = sigm (red[1] + gin[1]);
            float gv = ftanh(red[2] + gin[2]);
            float ov = sigm (red[3] + gin[3]);
            cst = fv * cst + iv * gv;
            h = ov * ftanh(cst);
            if (st < SEQ - 1) {
                float hub = __shfl_sync(0x00010001u, h, 16);
                if (lane == 0) {
                    unsigned long long hpk;
                    asm("mov.b64 %0, {%1, %2};" : "=l"(hpk)
                        : "r"(__float_as_uint(h)), "r"(__float_as_uint(hub)));
                    #pragma unroll
                    for (int r = 0; r < CPG; r++)
                        asm volatile("st.shared::cluster.b64 [%0], %1;"
                                     :: "r"(ra[nxt][r]), "l"(hpk) : "memory");
                }
            }
        }

        if (st < SEQ - 1) {
            __syncthreads();
            if (w == 0 && lane < 8)
                asm volatile("st.release.cluster.shared::cluster.u32 [%0], %1;"
                             :: "r"(fa), "r"((uint32_t)(st + 1)) : "memory");
        }

        // global h store AFTER the release: off the serial chain
        if (hl == 0)
            g_hcat[b * SEQ + t][d * HID + j] = h;
    }

    asm volatile("barrier.cluster.arrive.aligned;" ::: "memory");
    asm volatile("barrier.cluster.wait.aligned;"  ::: "memory");
}

// ------------------------- final assembly -----------------------------------
// out[b][k][m][n] = s_head[b,k,m] + s_tail[b,k,n] + sztab[k][clamp(n-m)]
__global__ void __launch_bounds__(256) assemble_kernel(float* __restrict__ out)
{
    int b = blockIdx.z, k = blockIdx.y, m0 = blockIdx.x * 16;
    int tid = threadIdx.x;
    __shared__ float st_s[SEQ];
    __shared__ float sz_s[NPOS];
    __shared__ float sh_s[16];
    for (int i = tid; i < SEQ; i += 256) st_s[i] = g_stail[b * SEQ + i][k];
    if (tid < NPOS) sz_s[tid] = g_sztab[k][tid];
    if (tid < 16)   sh_s[tid] = g_shead[b * SEQ + m0 + tid][k];
    __syncthreads();

    float* orow = out + (((size_t)(b * NOUT + k)) * SEQ + m0) * SEQ;
    #pragma unroll
    for (int it = 0; it < 8; it++) {
        int lin = it * 256 + tid;
        int r = lin >> 7;
        int n4 = (lin & 127) << 2;
        int m = m0 + r;
        float sh = sh_s[r];
        float4 v;
        int e;
        e = min(max(n4     - m, -15), 14) + 15; v.x = sh + st_s[n4    ] + sz_s[e];
        e = min(max(n4 + 1 - m, -15), 14) + 15; v.y = sh + st_s[n4 + 1] + sz_s[e];
        e = min(max(n4 + 2 - m, -15), 14) + 15; v.z = sh + st_s[n4 + 2] + sz_s[e];
        e = min(max(n4 + 3 - m, -15), 14) + 15; v.w = sh + st_s[n4 + 3] + sz_s[e];
        *reinterpret_cast<float4*>(orow + (size_t)r * SEQ + n4) = v;
    }
}

// ------------------------- launch -------------------------------------------
extern "C" void kernel_launch(void* const* d_in, const int* in_sizes, int n_in,
                              void* d_out, int out_size)
{
    const float* x      = (const float*)d_in[0];
    const float* Wih_f  = (const float*)d_in[1];
    const float* Whh_f  = (const float*)d_in[2];
    const float* bih_f  = (const float*)d_in[3];
    const float* bhh_f  = (const float*)d_in[4];
    const float* Wih_b  = (const float*)d_in[5];
    const float* Whh_b  = (const float*)d_in[6];
    const float* bih_b  = (const float*)d_in[7];
    const float* bhh_b  = (const float*)d_in[8];
    const float* W_head = (const float*)d_in[9];
    const float* b_head = (const float*)d_in[10];
    const float* W_tail = (const float*)d_in[11];
    const float* b_tail = (const float*)d_in[12];
    const float* emb    = (const float*)d_in[13];
    const float* W      = (const float*)d_in[14];
    float* out = (float*)d_out;

    float *pG, *pBias, *pHcat, *pHead, *pTail, *pShead, *pStail;
    cudaGetSymbolAddress((void**)&pG,     g_G);
    cudaGetSymbolAddress((void**)&pBias,  g_bias);
    cudaGetSymbolAddress((void**)&pHcat,  g_hcat);
    cudaGetSymbolAddress((void**)&pHead,  g_head);
    cudaGetSymbolAddress((void**)&pTail,  g_tail);
    cudaGetSymbolAddress((void**)&pShead, g_shead);
    cudaGetSymbolAddress((void**)&pStail, g_stail);

    prep_kernel<<<8, 256>>>(bih_f, bhh_f, bih_b, bhh_b, emb, W);

    // Stage 1: gate input projections (both directions)
    gemm_tf32<<<dim3(G4 / 64, ROWS / 64), 128>>>(x, D_IN, Wih_f, D_IN,
        pBias, 1, pG, G4, G4, D_IN, 0);
    gemm_tf32<<<dim3(G4 / 64, ROWS / 64), 128>>>(x, D_IN, Wih_b, D_IN,
        pBias + G4, 1, pG + (size_t)ROWS * G4, G4, G4, D_IN, 0);

    // Stage 2: recurrence (both directions, all batches in parallel)
    lstm_kernel<<<NGRP * CPG, 512>>>(Whh_f, Whh_b);

    // Stage 3: head / tail projections with leaky_relu
    gemm_tf32<<<dim3(MID / 64, ROWS / 64), 128>>>(pHcat, MID, W_head, MID,
        b_head, 1, pHead, MID, MID, MID, 1);
    gemm_tf32<<<dim3(MID / 64, ROWS / 64), 128>>>(pHcat, MID, W_tail, MID,
        b_tail, 1, pTail, MID, MID, MID, 1);

    // Stage 4: biaffine projections (k=50), bias = "ones" column of W
    gemm_tf32<<<dim3(1, ROWS / 64), 128>>>(pHead, MID, W, WLD,
        W + MID, WLD, pShead, NOUT, NOUT, MID, 0);
    gemm_tf32<<<dim3(1, ROWS / 64), 128>>>(pTail, MID, W + (MID + 1), WLD,
        W + (MID + 1) + MID, WLD, pStail, NOUT, NOUT, MID, 0);

    // Stage 5: assemble 210MB output
    assemble_kernel<<<dim3(SEQ / 16, NOUT, NB), 256>>>(out);
}

// round 7
// speedup vs baseline: 1.6695x; 1.6695x over previous
#include <cuda_runtime.h>
#include <cstdint>

#define D_IN 1024
#define HID  256
#define G4   1024
#define MID  512
#define SEQ  512
#define NB   4
#define NOUT 50
#define SED  64
#define NPOS 30
#define WLD  1090           // 2*(MID+1) + SED
#define ROWS 2048           // NB*SEQ
#define CPG  8              // CTAs per recurrence group (== cluster size)
#define UPC  32             // hidden units per CTA
#define NGRP 8              // 2 dirs * 4 batch
#define HPAD 132            // floats per K-half (128 + 4 pad, bank-shifts halves)
#define PSTR (2 * HPAD)     // floats per parity buffer

// ------------------------- scratch (static device memory) -------------------
__device__ float g_G[2][ROWS][G4];      // gate input preactivations (+bias)
__device__ float g_bias[2][G4];
__device__ float g_hcat[ROWS][MID];     // [b*SEQ+t][dir*HID + j]
__device__ float g_head[ROWS][MID];
__device__ float g_tail[ROWS][MID];
__device__ float g_shead[ROWS][NOUT];   // [(b,m)][k]
__device__ float g_stail[ROWS][NOUT];   // [(b,n)][k]
__device__ float g_sztab[NOUT][NPOS];

// ------------------------- prep: bias, size table ---------------------------
__global__ void prep_kernel(const float* __restrict__ bih_f, const float* __restrict__ bhh_f,
                            const float* __restrict__ bih_b, const float* __restrict__ bhh_b,
                            const float* __restrict__ emb,   const float* __restrict__ W)
{
    int g = blockIdx.x * blockDim.x + threadIdx.x;
    if (g < G4)            g_bias[0][g]      = bih_f[g]      + bhh_f[g];
    else if (g < 2 * G4)   g_bias[1][g - G4] = bih_b[g - G4] + bhh_b[g - G4];
    if (g < NOUT * NPOS) {
        int k = g / NPOS, p = g % NPOS;
        float s = 0.f;
        #pragma unroll 8
        for (int h = 0; h < SED; h++)
            s += emb[p * SED + h] * W[k * WLD + 2 * (MID + 1) + h];
        g_sztab[k][p] = s;
    }
}

// ------------------------- tf32 GEMM: C = A @ B^T (+bias, opt leaky) --------
__device__ __forceinline__ float to_tf32(float x) {
    uint32_t u;
    asm("cvt.rna.tf32.f32 %0, %1;" : "=r"(u) : "f"(x));
    return __uint_as_float(u);
}

__global__ void __launch_bounds__(128) gemm_tf32(
    const float* __restrict__ A, int lda,
    const float* __restrict__ Bw, int ldb,
    const float* __restrict__ bias, int bstr,
    float* __restrict__ C, int ldc,
    int N, int K, int act)
{
    __shared__ float As[64][33];
    __shared__ float Bs[64][33];
    int tid  = threadIdx.x;
    int warp = tid >> 5, lane = tid & 31;
    int gq = lane >> 2, tg = lane & 3;
    int wm = (warp >> 1) * 32, wn = (warp & 1) * 32;
    int bm = blockIdx.y * 64, bn = blockIdx.x * 64;

    float acc[2][4][4];
    #pragma unroll
    for (int a = 0; a < 2; a++)
        #pragma unroll
        for (int b = 0; b < 4; b++)
            #pragma unroll
            for (int c = 0; c < 4; c++) acc[a][b][c] = 0.f;

    bool bvec = ((ldb & 3) == 0);

    for (int k0 = 0; k0 < K; k0 += 32) {
        #pragma unroll
        for (int i = 0; i < 4; i++) {
            int l4 = tid + i * 128;
            int r = l4 >> 3, c4 = (l4 & 7) << 2;
            const float4 v = *reinterpret_cast<const float4*>(A + (size_t)(bm + r) * lda + k0 + c4);
            As[r][c4 + 0] = to_tf32(v.x); As[r][c4 + 1] = to_tf32(v.y);
            As[r][c4 + 2] = to_tf32(v.z); As[r][c4 + 3] = to_tf32(v.w);
        }
        #pragma unroll
        for (int i = 0; i < 4; i++) {
            int l4 = tid + i * 128;
            int r = l4 >> 3, c4 = (l4 & 7) << 2;
            float4 v;
            if (bn + r < N) {
                if (bvec) {
                    v = *reinterpret_cast<const float4*>(Bw + (size_t)(bn + r) * ldb + k0 + c4);
                } else {
                    const float* p = Bw + (size_t)(bn + r) * ldb + k0 + c4;
                    v = make_float4(p[0], p[1], p[2], p[3]);
                }
            } else v = make_float4(0.f, 0.f, 0.f, 0.f);
            Bs[r][c4 + 0] = to_tf32(v.x); Bs[r][c4 + 1] = to_tf32(v.y);
            Bs[r][c4 + 2] = to_tf32(v.z); Bs[r][c4 + 3] = to_tf32(v.w);
        }
        __syncthreads();

        #pragma unroll
        for (int kk = 0; kk < 32; kk += 8) {
            uint32_t af[2][4], bf[4][2];
            #pragma unroll
            for (int mf = 0; mf < 2; mf++) {
                int r0 = wm + mf * 16 + gq;
                af[mf][0] = __float_as_uint(As[r0    ][kk + tg]);
                af[mf][1] = __float_as_uint(As[r0 + 8][kk + tg]);
                af[mf][2] = __float_as_uint(As[r0    ][kk + tg + 4]);
                af[mf][3] = __float_as_uint(As[r0 + 8][kk + tg + 4]);
            }
            #pragma unroll
            for (int nf = 0; nf < 4; nf++) {
                int n0 = wn + nf * 8 + gq;
                bf[nf][0] = __float_as_uint(Bs[n0][kk + tg]);
                bf[nf][1] = __float_as_uint(Bs[n0][kk + tg + 4]);
            }
            #pragma unroll
            for (int mf = 0; mf < 2; mf++)
                #pragma unroll
                for (int nf = 0; nf < 4; nf++)
                    asm volatile(
                        "mma.sync.aligned.m16n8k8.row.col.f32.tf32.tf32.f32 "
                        "{%0,%1,%2,%3}, {%4,%5,%6,%7}, {%8,%9}, {%0,%1,%2,%3};\n"
                        : "+f"(acc[mf][nf][0]), "+f"(acc[mf][nf][1]),
                          "+f"(acc[mf][nf][2]), "+f"(acc[mf][nf][3])
                        : "r"(af[mf][0]), "r"(af[mf][1]), "r"(af[mf][2]), "r"(af[mf][3]),
                          "r"(bf[nf][0]), "r"(bf[nf][1]));
        }
        __syncthreads();
    }

    #pragma unroll
    for (int mf = 0; mf < 2; mf++) {
        #pragma unroll
        for (int nf = 0; nf < 4; nf++) {
            int row = bm + wm + mf * 16 + gq;
            int col = bn + wn + nf * 8 + tg * 2;
            #pragma unroll
            for (int q = 0; q < 4; q++) {
                int r = row + (q >> 1) * 8;
                int c = col + (q & 1);
                if (c < N) {
                    float v = acc[mf][nf][q] + (bias ? bias[(size_t)c * bstr] : 0.f);
                    if (act) v = v > 0.f ? v : 0.01f * v;
                    C[(size_t)r * ldc + c] = v;
                }
            }
        }
    }
}

// ------------------------- LSTM recurrence ----------------------------------
// 8 groups (dir,batch), each = one 8-CTA cluster. CTA owns 32 units (128 gate
// rows). 256 threads: thread = (row 0..127, K-half). 64 fma2 + ONE shfl per
// thread per step. Warp 0 combines gates (4 per lane) via a 128-float smem
// exchange, pushes h warp-wide (lane = rank*4+seg, 32B each), releases flags.
__device__ __forceinline__ float sigm(float x) { return 1.f / (1.f + __expf(-x)); }
__device__ __forceinline__ float ftanh(float x) {
    float e = __expf(2.f * x);
    return 1.f - __fdividef(2.f, e + 1.f);
}
__device__ __forceinline__ void fma2(unsigned long long& acc,
                                     unsigned long long a, unsigned long long b) {
    asm("fma.rn.f32x2 %0, %1, %2, %0;" : "+l"(acc) : "l"(a), "l"(b));
}
__device__ __forceinline__ void add2(unsigned long long& a, unsigned long long b) {
    asm("add.rn.f32x2 %0, %0, %1;" : "+l"(a) : "l"(b));
}
__device__ __forceinline__ float pairsum(unsigned long long p) {
    uint32_t lo, hi;
    asm("mov.b64 {%0,%1}, %2;" : "=r"(lo), "=r"(hi) : "l"(p));
    return __uint_as_float(lo) + __uint_as_float(hi);
}

__global__ void __launch_bounds__(256, 1) __cluster_dims__(CPG, 1, 1)
lstm_kernel(const float* __restrict__ Whh_f, const float* __restrict__ Whh_b)
{
    __shared__ __align__(16) float    hs2[2][PSTR];
    __shared__ __align__(16) float    red[128];
    __shared__ __align__(16) float    hstage[UPC];
    __shared__ __align__(16) uint32_t flags[CPG];

    int grp = blockIdx.x / CPG;
    uint32_t cig;
    asm("mov.u32 %0, %%cluster_ctarank;" : "=r"(cig));
    int d = grp >> 2, b = grp & 3;
    int tid  = threadIdx.x;
    int w    = tid >> 5;
    int lane = tid & 31;
    int row  = w * 16 + (lane & 15);   // gate row 0..127 within CTA
    int kh   = lane >> 4;              // K half
    int gi   = row >> 5;               // gate 0..3
    int ul   = row & 31;               // unit within CTA
    int j    = (int)cig * UPC + ul;    // global unit
    int grow = gi * HID + j;           // Whh row / G column
    const float* Whh = d ? Whh_b : Whh_f;
    const float* Gd  = &g_G[d][0][0];

    // weights: this thread's K-half of one gate row = 32 ulonglong2
    ulonglong2 w2[32];
    #pragma unroll
    for (int q = 0; q < 32; q++)
        w2[q] = *reinterpret_cast<const ulonglong2*>(
            &Whh[(size_t)grow * HID + kh * 128 + q * 4]);

    for (int i = tid; i < 2 * PSTR; i += 256) ((float*)hs2)[i] = 0.f;
    if (tid < CPG) flags[tid] = 0u;
    __syncthreads();
    asm volatile("barrier.cluster.arrive.aligned;" ::: "memory");
    asm volatile("barrier.cluster.wait.aligned;"  ::: "memory");

    uint32_t hs_u32  = (uint32_t)__cvta_generic_to_shared(&hs2[0][0]);
    uint32_t flg_u32 = (uint32_t)__cvta_generic_to_shared(&flags[0]);
    uint32_t my_flag_addr = flg_u32 + (uint32_t)(lane & 7) * 4u;

    // push dst: this CTA's 32-float slot in each rank's hs2, split 4x32B
    int ds = (int)cig * UPC + ((int)cig >= 4 ? 4 : 0);   // float offset in parity buf
    uint32_t ra[2];
    {
        int rnk = (lane >> 2) & 7, seg = lane & 3;
        #pragma unroll
        for (int P = 0; P < 2; P++) {
            uint32_t laddr = hs_u32 + (uint32_t)(P * PSTR + ds) * 4u + (uint32_t)seg * 32u;
            asm("mapa.shared::cluster.u32 %0, %1, %2;"
                : "=r"(ra[P]) : "r"(laddr), "r"(rnk));
        }
    }
    uint32_t fa;
    {
        uint32_t laddr = flg_u32 + cig * 4u;
        asm("mapa.shared::cluster.u32 %0, %1, %2;"
            : "=r"(fa) : "r"(laddr), "r"(lane & 7));
    }

    float cst = 0.f;

    for (int st = 0; st < SEQ; st++) {
        int t = d ? (SEQ - 1 - st) : st;
        int cur = st & 1, nxt = cur ^ 1;

        // prefetch this row's preactivation before the wait
        float gin = 0.f;
        if (kh == 0)
            gin = __ldg(&Gd[(size_t)(b * SEQ + t) * G4 + grow]);

        // warp 0 polls flags; all others park at the barrier
        if (w == 0) {
            uint32_t tgt = (uint32_t)st;
            while (true) {
                uint32_t f = 0xffffffffu;
                if (lane < 8)
                    asm volatile("ld.acquire.cluster.shared::cta.u32 %0, [%1];"
                                 : "=r"(f) : "r"(my_flag_addr));
                if (__all_sync(0xffffffffu, f >= tgt)) break;
            }
        }
        __syncthreads();

        // matvec: one gate row, this K-half (64 fma2)
        const float* hb = &hs2[cur][kh * HPAD];
        unsigned long long acc[4] = {0ull, 0ull, 0ull, 0ull};
        #pragma unroll
        for (int q = 0; q < 32; q++) {
            const ulonglong2 hv = *reinterpret_cast<const ulonglong2*>(hb + q * 4);
            fma2(acc[q & 3], w2[q].x, hv.x);
            fma2(acc[q & 3], w2[q].y, hv.y);
        }
        add2(acc[0], acc[2]); add2(acc[1], acc[3]); add2(acc[0], acc[1]);
        float s = pairsum(acc[0]);
        s += __shfl_xor_sync(0xffffffffu, s, 16);
        if (kh == 0) red[row] = s + gin;
        __syncthreads();

        if (w == 0) {
            float pi = red[lane], pf = red[32 + lane], pg = red[64 + lane], po = red[96 + lane];
            float iv = sigm(pi), fv = sigm(pf), gv = ftanh(pg), ov = sigm(po);
            cst = fv * cst + iv * gv;
            float h = ov * ftanh(cst);
            hstage[lane] = h;
            __syncwarp();
            if (st < SEQ - 1) {
                int seg = lane & 3;
                const ulonglong2* sp = reinterpret_cast<const ulonglong2*>(hstage) + seg * 2;
                ulonglong2 v0 = sp[0], v1 = sp[1];
                uint32_t dst = ra[nxt];
                asm volatile("st.shared::cluster.b64 [%0], %1;" :: "r"(dst      ), "l"(v0.x) : "memory");
                asm volatile("st.shared::cluster.b64 [%0], %1;" :: "r"(dst +  8u), "l"(v0.y) : "memory");
                asm volatile("st.shared::cluster.b64 [%0], %1;" :: "r"(dst + 16u), "l"(v1.x) : "memory");
                asm volatile("st.shared::cluster.b64 [%0], %1;" :: "r"(dst + 24u), "l"(v1.y) : "memory");
                __syncwarp();
                if (lane < 8)
                    asm volatile("st.release.cluster.shared::cluster.u32 [%0], %1;"
                                 :: "r"(fa), "r"((uint32_t)(st + 1)) : "memory");
            }
            // global h store after the release: off the serial chain
            g_hcat[b * SEQ + t][d * HID + (int)cig * UPC + lane] = h;
        }
    }

    asm volatile("barrier.cluster.arrive.aligned;" ::: "memory");
    asm volatile("barrier.cluster.wait.aligned;"  ::: "memory");
}

// ------------------------- final assembly -----------------------------------
// out[b][k][m][n] = s_head[b,k,m] + s_tail[b,k,n] + sztab[k][clamp(n-m)]
__global__ void __launch_bounds__(256) assemble_kernel(float* __restrict__ out)
{
    int b = blockIdx.z, k = blockIdx.y, m0 = blockIdx.x * 16;
    int tid = threadIdx.x;
    __shared__ float st_s[SEQ];
    __shared__ float sz_s[NPOS];
    __shared__ float sh_s[16];
    for (int i = tid; i < SEQ; i += 256) st_s[i] = g_stail[b * SEQ + i][k];
    if (tid < NPOS) sz_s[tid] = g_sztab[k][tid];
    if (tid < 16)   sh_s[tid] = g_shead[b * SEQ + m0 + tid][k];
    __syncthreads();

    float* orow = out + (((size_t)(b * NOUT + k)) * SEQ + m0) * SEQ;
    #pragma unroll
    for (int it = 0; it < 8; it++) {
        int lin = it * 256 + tid;
        int r = lin >> 7;
        int n4 = (lin & 127) << 2;
        int m = m0 + r;
        float sh = sh_s[r];
        float4 v;
        int e;
        e = min(max(n4     - m, -15), 14) + 15; v.x = sh + st_s[n4    ] + sz_s[e];
        e = min(max(n4 + 1 - m, -15), 14) + 15; v.y = sh + st_s[n4 + 1] + sz_s[e];
        e = min(max(n4 + 2 - m, -15), 14) + 15; v.z = sh + st_s[n4 + 2] + sz_s[e];
        e = min(max(n4 + 3 - m, -15), 14) + 15; v.w = sh + st_s[n4 + 3] + sz_s[e];
        *reinterpret_cast<float4*>(orow + (size_t)r * SEQ + n4) = v;
    }
}

// ------------------------- launch -------------------------------------------
extern "C" void kernel_launch(void* const* d_in, const int* in_sizes, int n_in,
                              void* d_out, int out_size)
{
    const float* x      = (const float*)d_in[0];
    const float* Wih_f  = (const float*)d_in[1];
    const float* Whh_f  = (const float*)d_in[2];
    const float* bih_f  = (const float*)d_in[3];
    const float* bhh_f  = (const float*)d_in[4];
    const float* Wih_b  = (const float*)d_in[5];
    const float* Whh_b  = (const float*)d_in[6];
    const float* bih_b  = (const float*)d_in[7];
    const float* bhh_b  = (const float*)d_in[8];
    const float* W_head = (const float*)d_in[9];
    const float* b_head = (const float*)d_in[10];
    const float* W_tail = (const float*)d_in[11];
    const float* b_tail = (const float*)d_in[12];
    const float* emb    = (const float*)d_in[13];
    const float* W      = (const float*)d_in[14];
    float* out = (float*)d_out;

    float *pG, *pBias, *pHcat, *pHead, *pTail, *pShead, *pStail;
    cudaGetSymbolAddress((void**)&pG,     g_G);
    cudaGetSymbolAddress((void**)&pBias,  g_bias);
    cudaGetSymbolAddress((void**)&pHcat,  g_hcat);
    cudaGetSymbolAddress((void**)&pHead,  g_head);
    cudaGetSymbolAddress((void**)&pTail,  g_tail);
    cudaGetSymbolAddress((void**)&pShead, g_shead);
    cudaGetSymbolAddress((void**)&pStail, g_stail);

    prep_kernel<<<8, 256>>>(bih_f, bhh_f, bih_b, bhh_b, emb, W);

    // Stage 1: gate input projections (both directions)
    gemm_tf32<<<dim3(G4 / 64, ROWS / 64), 128>>>(x, D_IN, Wih_f, D_IN,
        pBias, 1, pG, G4, G4, D_IN, 0);
    gemm_tf32<<<dim3(G4 / 64, ROWS / 64), 128>>>(x, D_IN, Wih_b, D_IN,
        pBias + G4, 1, pG + (size_t)ROWS * G4, G4, G4, D_IN, 0);

    // Stage 2: recurrence (both directions, all batches in parallel)
    lstm_kernel<<<NGRP * CPG, 256>>>(Whh_f, Whh_b);

    // Stage 3: head / tail projections with leaky_relu
    gemm_tf32<<<dim3(MID / 64, ROWS / 64), 128>>>(pHcat, MID, W_head, MID,
        b_head, 1, pHead, MID, MID, MID, 1);
    gemm_tf32<<<dim3(MID / 64, ROWS / 64), 128>>>(pHcat, MID, W_tail, MID,
        b_tail, 1, pTail, MID, MID, MID, 1);

    // Stage 4: biaffine projections (k=50), bias = "ones" column of W
    gemm_tf32<<<dim3(1, ROWS / 64), 128>>>(pHead, MID, W, WLD,
        W + MID, WLD, pShead, NOUT, NOUT, MID, 0);
    gemm_tf32<<<dim3(1, ROWS / 64), 128>>>(pTail, MID, W + (MID + 1), WLD,
        W + (MID + 1) + MID, WLD, pStail, NOUT, NOUT, MID, 0);

    // Stage 5: assemble 210MB output
    assemble_kernel<<<dim3(SEQ / 16, NOUT, NB), 256>>>(out);
}